// round 10
// baseline (speedup 1.0000x reference)
#include <cuda_runtime.h>
#include <cuda_bf16.h>
#include <cstdint>

#define DEVINL __device__ __forceinline__

namespace {

constexpr int Bb = 2, Hh = 16, Ss = 2048, Dd = 128;
constexpr int TM = 128;           // query tile
constexpr int TN = 128;           // key tile
constexpr int NKT = Ss / TN;      // 16
constexpr int NTHREADS = 256;     // 8 warps, 16 rows each
constexpr int ROWB = 272;         // 128 bf16 * 2B + 16B pad (conflict-free ldmatrix)
constexpr int TILE_B = 128 * ROWB;            // 34816
constexpr uint32_t SMEM_BYTES = 6 * TILE_B;   // 208896 (QH QL KH KL VH VL)

constexpr size_t NELEM = (size_t)Bb * Hh * Ss * Dd;  // 8,388,608 per tensor

}  // namespace

// 64 MB of pre-converted bf16 hi/lo planes for K and V (static scratch — legal)
__device__ __align__(16) __nv_bfloat16 g_KH[NELEM];
__device__ __align__(16) __nv_bfloat16 g_KL[NELEM];
__device__ __align__(16) __nv_bfloat16 g_VH[NELEM];
__device__ __align__(16) __nv_bfloat16 g_VL[NELEM];

namespace {

DEVINL uint32_t smem_u32(const void* p) {
  uint32_t a;
  asm("{ .reg .u64 t; cvta.to.shared.u64 t, %1; cvt.u32.u64 %0, t; }" : "=r"(a) : "l"(p));
  return a;
}

DEVINL uint32_t toff(int r, int c) { return (uint32_t)(r * ROWB + c * 2); }

// ---------------- fp32 -> bf16 hi/lo split ----------------
DEVINL void split2(float x, __nv_bfloat16& h, __nv_bfloat16& l) {
  h = __float2bfloat16(x);
  l = __float2bfloat16(x - __bfloat162float(h));
}
DEVINL uint32_t pack2(__nv_bfloat16 lo_el, __nv_bfloat16 hi_el) {
  return ((uint32_t)__bfloat16_as_ushort(hi_el) << 16) | (uint32_t)__bfloat16_as_ushort(lo_el);
}

// store 4 consecutive cols of one row into hi/lo tiles (8B chunks)
DEVINL void store_hl4(char* hB, char* lB, int row, int col, float4 val) {
  __nv_bfloat16 h0, h1, h2, h3, l0, l1, l2, l3;
  split2(val.x, h0, l0); split2(val.y, h1, l1);
  split2(val.z, h2, l2); split2(val.w, h3, l3);
  uint32_t off = toff(row, col);
  *reinterpret_cast<uint2*>(hB + off) = make_uint2(pack2(h0, h1), pack2(h2, h3));
  *reinterpret_cast<uint2*>(lB + off) = make_uint2(pack2(l0, l1), pack2(l2, l3));
}

// ---------------- cp.async helpers ----------------
DEVINL void cp16(uint32_t dst, const void* src) {
  asm volatile("cp.async.cg.shared.global [%0], [%1], 16;" :: "r"(dst), "l"(src));
}
#define CP_COMMIT() asm volatile("cp.async.commit_group;" ::: "memory")
#define CP_WAIT1()  asm volatile("cp.async.wait_group 1;" ::: "memory")

// copy one [128 x 128] bf16 hi/lo tile pair gmem -> padded smem (16 cp.async/thread each)
DEVINL void load_tile_pair(uint32_t dstH, uint32_t dstL,
                           const __nv_bfloat16* srcH, const __nv_bfloat16* srcL,
                           int tid) {
#pragma unroll
  for (int i = 0; i < 8; ++i) {
    int c = tid + i * NTHREADS;       // chunk id: 2048 chunks of 16B
    int row = c >> 4, ch = c & 15;
    cp16(dstH + (uint32_t)(row * ROWB + ch * 16), srcH + row * Dd + ch * 8);
    cp16(dstL + (uint32_t)(row * ROWB + ch * 16), srcL + row * Dd + ch * 8);
  }
}

// ---------------- MMA / ldmatrix wrappers ----------------
DEVINL void ldsm4(uint32_t* r, uint32_t addr) {
  asm volatile("ldmatrix.sync.aligned.m8n8.x4.shared.b16 {%0,%1,%2,%3}, [%4];"
               : "=r"(r[0]), "=r"(r[1]), "=r"(r[2]), "=r"(r[3]) : "r"(addr));
}
DEVINL void ldsm4t(uint32_t* r, uint32_t addr) {
  asm volatile("ldmatrix.sync.aligned.m8n8.x4.trans.shared.b16 {%0,%1,%2,%3}, [%4];"
               : "=r"(r[0]), "=r"(r[1]), "=r"(r[2]), "=r"(r[3]) : "r"(addr));
}
// non-volatile — pure register op; lets ptxas schedule/interleave HMMAs.
DEVINL void mma16816(float* c, const uint32_t* a, uint32_t b0, uint32_t b1) {
  asm("mma.sync.aligned.m16n8k16.row.col.f32.bf16.bf16.f32 "
      "{%0,%1,%2,%3}, {%4,%5,%6,%7}, {%8,%9}, {%0,%1,%2,%3};"
      : "+f"(c[0]), "+f"(c[1]), "+f"(c[2]), "+f"(c[3])
      : "r"(a[0]), "r"(a[1]), "r"(a[2]), "r"(a[3]), "r"(b0), "r"(b1));
}

// ---------------- pre-pass: fp32 K,V -> bf16 hi/lo planes ----------------
__global__ void __launch_bounds__(256)
conv_kernel(const float* __restrict__ k, const float* __restrict__ v) {
  size_t i = (size_t)blockIdx.x * 256 + threadIdx.x;  // float4 index
  float4 a = ((const float4*)k)[i];
  float4 b = ((const float4*)v)[i];
  __nv_bfloat16 h0, h1, h2, h3, l0, l1, l2, l3;
  split2(a.x, h0, l0); split2(a.y, h1, l1); split2(a.z, h2, l2); split2(a.w, h3, l3);
  ((uint2*)g_KH)[i] = make_uint2(pack2(h0, h1), pack2(h2, h3));
  ((uint2*)g_KL)[i] = make_uint2(pack2(l0, l1), pack2(l2, l3));
  split2(b.x, h0, l0); split2(b.y, h1, l1); split2(b.z, h2, l2); split2(b.w, h3, l3);
  ((uint2*)g_VH)[i] = make_uint2(pack2(h0, h1), pack2(h2, h3));
  ((uint2*)g_VL)[i] = make_uint2(pack2(l0, l1), pack2(l2, l3));
}

__global__ void __launch_bounds__(NTHREADS, 1)
attn_mask_kernel(const float* __restrict__ q, const float* __restrict__ mask,
                 float* __restrict__ out) {
  extern __shared__ char smem[];
  const uint32_t sb = smem_u32(smem);
  const int tid = threadIdx.x, wid = tid >> 5, lane = tid & 31;
  const int bh = (int)blockIdx.z * Hh + (int)blockIdx.y;
  const int s0 = (int)blockIdx.x * TM;

  char* QH = smem;
  char* QL = smem + TILE_B;
  const uint32_t sKH = sb + 2 * TILE_B;
  const uint32_t sKL = sb + 3 * TILE_B;
  const uint32_t sVH = sb + 4 * TILE_B;
  const uint32_t sVL = sb + 5 * TILE_B;

  const __nv_bfloat16* kh = g_KH + (size_t)bh * Ss * Dd;
  const __nv_bfloat16* kl = g_KL + (size_t)bh * Ss * Dd;
  const __nv_bfloat16* vh = g_VH + (size_t)bh * Ss * Dd;
  const __nv_bfloat16* vl = g_VL + (size_t)bh * Ss * Dd;

  // ---- load + split Q tile (once) ----
  {
    const float4* qsrc = (const float4*)(q + ((size_t)bh * Ss + s0) * Dd);
#pragma unroll
    for (int i = 0; i < 16; ++i) {
      int f = tid + i * NTHREADS;
      float4 val = qsrc[f];
      int e = f * 4;
      store_hl4(QH, QL, e >> 7, e & 127, val);
    }
  }

  // ---- prologue: async-load tile 0 K and V ----
  load_tile_pair(sKH, sKL, kh, kl, tid);
  CP_COMMIT();
  load_tile_pair(sVH, sVL, vh, vl, tid);
  CP_COMMIT();
  CP_WAIT1();          // K(0) done (V(0) may be in flight)
  __syncthreads();

  // accumulators: S/P [16 n-frags][4], O [16 n-frags][4]
  float S[16][4];
  float O[16][4];
#pragma unroll
  for (int i = 0; i < 16; ++i) { O[i][0] = O[i][1] = O[i][2] = O[i][3] = 0.f; }

  const int wrow0 = wid * 16;
  const int lrow = lane & 7;
  const int lq = (lane >> 3) & 1;
  const int lh = lane >> 4;

  // ldmatrix lane base addresses
  const uint32_t qA_h = sb + 0 * TILE_B + toff(wrow0 + lrow + lq * 8, lh * 8);
  const uint32_t qA_l = qA_h + TILE_B;
  const uint32_t kB_h = sKH + toff(lrow + lh * 8, lq * 8);
  const uint32_t kB_l = kB_h + TILE_B;
  const uint32_t vB_h = sVH + toff(lrow + lq * 8, lh * 8);
  const uint32_t vB_l = vB_h + TILE_B;

  const int mr = wrow0 + (lane >> 2);      // this thread's row (and +8)
  const int mc = (lane & 3) * 2;           // col offset within an 8-wide n-frag
  const float* mbase = mask + ((size_t)bh * Ss + (s0 + mr)) * Ss;

#pragma unroll 1
  for (int kt = 0; kt < NKT; ++kt) {
    const int t0 = kt * TN;
    const int tn = (kt + 1 < NKT) ? (kt + 1) * TN : 0;  // clamp (harmless reload)

    // ---- mask pipeline prologue: buffers for GEMM2 kk=0,1 (consumed late) ----
    float2 mb[2][4];
#pragma unroll
    for (int s = 0; s < 2; ++s) {
      const float* mp0 = mbase + t0 + (2 * s) * 8 + mc;
      const float* mp1 = mbase + t0 + (2 * s + 1) * 8 + mc;
      mb[s][0] = __ldcs((const float2*)mp0);
      mb[s][1] = __ldcs((const float2*)(mp0 + 8 * Ss));
      mb[s][2] = __ldcs((const float2*)mp1);
      mb[s][3] = __ldcs((const float2*)(mp1 + 8 * Ss));
    }

    // ---- GEMM1: S = Q @ K^T (3-term bf16 split, interleaved accumulators) ----
#pragma unroll
    for (int i = 0; i < 16; ++i) { S[i][0] = S[i][1] = S[i][2] = S[i][3] = 0.f; }
#pragma unroll
    for (int kk = 0; kk < 8; ++kk) {
      uint32_t ah[4], al[4];
      ldsm4(ah, qA_h + kk * 32);
      ldsm4(al, qA_l + kk * 32);
#pragma unroll
      for (int ntp = 0; ntp < 8; ++ntp) {
        uint32_t bh_[4], bl_[4];
        ldsm4(bh_, kB_h + (uint32_t)(ntp * 16 * ROWB) + kk * 32);
        ldsm4(bl_, kB_l + (uint32_t)(ntp * 16 * ROWB) + kk * 32);
        mma16816(S[2 * ntp],     ah, bh_[0], bh_[1]);
        mma16816(S[2 * ntp + 1], ah, bh_[2], bh_[3]);
        mma16816(S[2 * ntp],     ah, bl_[0], bl_[1]);
        mma16816(S[2 * ntp + 1], ah, bl_[2], bl_[3]);
        mma16816(S[2 * ntp],     al, bh_[0], bh_[1]);
        mma16816(S[2 * ntp + 1], al, bh_[2], bh_[3]);
      }
    }

    __syncthreads();  // all warps done reading K tile

    // ---- issue next K tile (overlaps GEMM2) ----
    load_tile_pair(sKH, sKL, kh + (size_t)tn * Dd, kl + (size_t)tn * Dd, tid);
    CP_COMMIT();
    CP_WAIT1();       // V(kt) done (next-K outstanding)
    __syncthreads();

    // ---- GEMM2: O += (S*mask) @ V; mask applied per kk from pipelined bufs ----
#pragma unroll
    for (int kk = 0; kk < 8; ++kk) {
      // apply mask buffer (loaded >=2 steps ago) to S[2kk], S[2kk+1]
      {
        const float2* m = mb[kk & 1];
        S[2 * kk][0] *= m[0].x;     S[2 * kk][1] *= m[0].y;
        S[2 * kk][2] *= m[1].x;     S[2 * kk][3] *= m[1].y;
        S[2 * kk + 1][0] *= m[2].x; S[2 * kk + 1][1] *= m[2].y;
        S[2 * kk + 1][2] *= m[3].x; S[2 * kk + 1][3] *= m[3].y;
      }
      // refill this buffer for step kk+2 (latency hidden under the MMA block)
      if (kk + 2 < 8) {
        const int nf0 = 2 * (kk + 2), nf1 = nf0 + 1;
        const float* mp0 = mbase + t0 + nf0 * 8 + mc;
        const float* mp1 = mbase + t0 + nf1 * 8 + mc;
        mb[kk & 1][0] = __ldcs((const float2*)mp0);
        mb[kk & 1][1] = __ldcs((const float2*)(mp0 + 8 * Ss));
        mb[kk & 1][2] = __ldcs((const float2*)mp1);
        mb[kk & 1][3] = __ldcs((const float2*)(mp1 + 8 * Ss));
      }
      // build P A-fragments for this k-step from S n-frags 2kk, 2kk+1
      uint32_t ph[4], pl[4];
      {
        __nv_bfloat16 h0, h1, h2, h3, l0, l1, l2, l3;
        split2(S[2 * kk][0], h0, l0); split2(S[2 * kk][1], h1, l1);
        split2(S[2 * kk][2], h2, l2); split2(S[2 * kk][3], h3, l3);
        ph[0] = pack2(h0, h1); ph[1] = pack2(h2, h3);
        pl[0] = pack2(l0, l1); pl[1] = pack2(l2, l3);
        split2(S[2 * kk + 1][0], h0, l0); split2(S[2 * kk + 1][1], h1, l1);
        split2(S[2 * kk + 1][2], h2, l2); split2(S[2 * kk + 1][3], h3, l3);
        ph[2] = pack2(h0, h1); ph[3] = pack2(h2, h3);
        pl[2] = pack2(l0, l1); pl[3] = pack2(l2, l3);
      }
#pragma unroll
      for (int np = 0; np < 8; ++np) {
        uint32_t bh_[4], bl_[4];
        ldsm4t(bh_, vB_h + (uint32_t)(kk * 16 * ROWB) + np * 32);
        ldsm4t(bl_, vB_l + (uint32_t)(kk * 16 * ROWB) + np * 32);
        mma16816(O[2 * np],     ph, bh_[0], bh_[1]);
        mma16816(O[2 * np + 1], ph, bh_[2], bh_[3]);
        mma16816(O[2 * np],     ph, bl_[0], bl_[1]);
        mma16816(O[2 * np + 1], ph, bl_[2], bl_[3]);
        mma16816(O[2 * np],     pl, bh_[0], bh_[1]);
        mma16816(O[2 * np + 1], pl, bh_[2], bh_[3]);
      }
    }

    __syncthreads();  // all warps done reading V tile

    // ---- issue next V tile (overlaps next GEMM1) ----
    load_tile_pair(sVH, sVL, vh + (size_t)tn * Dd, vl + (size_t)tn * Dd, tid);
    CP_COMMIT();
    CP_WAIT1();       // next-K done (next-V outstanding)
    __syncthreads();
  }

  // ---- epilogue: O regs -> gmem ----
  {
    float* ob = out + ((size_t)bh * Ss + (s0 + mr)) * Dd + mc;
#pragma unroll
    for (int nf = 0; nf < 16; ++nf) {
      *(float2*)(ob + nf * 8) = make_float2(O[nf][0], O[nf][1]);
      *(float2*)(ob + 8 * Dd + nf * 8) = make_float2(O[nf][2], O[nf][3]);
    }
  }
}

}  // namespace

extern "C" void kernel_launch(void* const* d_in, const int* in_sizes, int n_in,
                              void* d_out, int out_size) {
  (void)in_sizes; (void)n_in; (void)out_size;
  const float* q = (const float*)d_in[0];
  const float* k = (const float*)d_in[1];
  const float* v = (const float*)d_in[2];
  const float* m = (const float*)d_in[3];
  float* out = (float*)d_out;

  // pre-pass: convert K, V to bf16 hi/lo planes (NELEM/4 float4s, 256 thr/blk)
  conv_kernel<<<(int)(NELEM / 4 / 256), 256>>>(k, v);

  cudaFuncSetAttribute(attn_mask_kernel, cudaFuncAttributeMaxDynamicSharedMemorySize,
                       SMEM_BYTES);
  dim3 grid(Ss / TM, Hh, Bb);
  attn_mask_kernel<<<grid, NTHREADS, SMEM_BYTES>>>(q, m, out);
}

// round 12
// speedup vs baseline: 1.0112x; 1.0112x over previous
#include <cuda_runtime.h>
#include <cuda_bf16.h>
#include <cstdint>

#define DEVINL __device__ __forceinline__

namespace {

constexpr int Bb = 2, Hh = 16, Ss = 2048, Dd = 128;
constexpr int TM = 128;           // query tile
constexpr int TN = 128;           // key tile
constexpr int NKT = Ss / TN;      // 16
constexpr int NTHREADS = 512;     // 16 warps: 8 row-strips x 2 t-halves
constexpr int ROWB = 272;         // 128 bf16 * 2B + 16B pad (conflict-free ldmatrix)
constexpr int TILE_B = 128 * ROWB;            // 34816
constexpr uint32_t SMEM_BYTES = 6 * TILE_B;   // 208896 (QH QL KH KL VH VL)

constexpr size_t NELEM = (size_t)Bb * Hh * Ss * Dd;  // 8,388,608 per tensor

}  // namespace

// 64 MB of pre-converted bf16 hi/lo planes for K and V (static scratch — legal)
__device__ __align__(16) __nv_bfloat16 g_KH[NELEM];
__device__ __align__(16) __nv_bfloat16 g_KL[NELEM];
__device__ __align__(16) __nv_bfloat16 g_VH[NELEM];
__device__ __align__(16) __nv_bfloat16 g_VL[NELEM];

namespace {

DEVINL uint32_t smem_u32(const void* p) {
  uint32_t a;
  asm("{ .reg .u64 t; cvta.to.shared.u64 t, %1; cvt.u32.u64 %0, t; }" : "=r"(a) : "l"(p));
  return a;
}

DEVINL uint32_t toff(int r, int c) { return (uint32_t)(r * ROWB + c * 2); }

// ---------------- fp32 -> bf16 hi/lo split ----------------
DEVINL void split2(float x, __nv_bfloat16& h, __nv_bfloat16& l) {
  h = __float2bfloat16(x);
  l = __float2bfloat16(x - __bfloat162float(h));
}
DEVINL uint32_t pack2(__nv_bfloat16 lo_el, __nv_bfloat16 hi_el) {
  return ((uint32_t)__bfloat16_as_ushort(hi_el) << 16) | (uint32_t)__bfloat16_as_ushort(lo_el);
}

// store 4 consecutive cols of one row into hi/lo tiles (8B chunks)
DEVINL void store_hl4(char* hB, char* lB, int row, int col, float4 val) {
  __nv_bfloat16 h0, h1, h2, h3, l0, l1, l2, l3;
  split2(val.x, h0, l0); split2(val.y, h1, l1);
  split2(val.z, h2, l2); split2(val.w, h3, l3);
  uint32_t off = toff(row, col);
  *reinterpret_cast<uint2*>(hB + off) = make_uint2(pack2(h0, h1), pack2(h2, h3));
  *reinterpret_cast<uint2*>(lB + off) = make_uint2(pack2(l0, l1), pack2(l2, l3));
}

// ---------------- cp.async helpers ----------------
DEVINL void cp16(uint32_t dst, const void* src) {
  asm volatile("cp.async.cg.shared.global [%0], [%1], 16;" :: "r"(dst), "l"(src));
}
#define CP_COMMIT()  asm volatile("cp.async.commit_group;" ::: "memory")
#define CP_WAIT1()   asm volatile("cp.async.wait_group 1;" ::: "memory")
#define CP_WAIT0()   asm volatile("cp.async.wait_group 0;" ::: "memory")

// copy one [128 x 128] bf16 hi/lo tile pair gmem -> padded smem (4 cp.async/thread each)
DEVINL void load_tile_pair(uint32_t dstH, uint32_t dstL,
                           const __nv_bfloat16* srcH, const __nv_bfloat16* srcL,
                           int tid) {
#pragma unroll
  for (int i = 0; i < 4; ++i) {
    int c = tid + i * NTHREADS;       // chunk id: 2048 chunks of 16B
    int row = c >> 4, ch = c & 15;
    cp16(dstH + (uint32_t)(row * ROWB + ch * 16), srcH + row * Dd + ch * 8);
    cp16(dstL + (uint32_t)(row * ROWB + ch * 16), srcL + row * Dd + ch * 8);
  }
}

// ---------------- MMA / ldmatrix wrappers ----------------
DEVINL void ldsm4(uint32_t* r, uint32_t addr) {
  asm volatile("ldmatrix.sync.aligned.m8n8.x4.shared.b16 {%0,%1,%2,%3}, [%4];"
               : "=r"(r[0]), "=r"(r[1]), "=r"(r[2]), "=r"(r[3]) : "r"(addr));
}
DEVINL void ldsm4t(uint32_t* r, uint32_t addr) {
  asm volatile("ldmatrix.sync.aligned.m8n8.x4.trans.shared.b16 {%0,%1,%2,%3}, [%4];"
               : "=r"(r[0]), "=r"(r[1]), "=r"(r[2]), "=r"(r[3]) : "r"(addr));
}
// non-volatile — pure register op; lets ptxas schedule/interleave HMMAs.
DEVINL void mma16816(float* c, const uint32_t* a, uint32_t b0, uint32_t b1) {
  asm("mma.sync.aligned.m16n8k16.row.col.f32.bf16.bf16.f32 "
      "{%0,%1,%2,%3}, {%4,%5,%6,%7}, {%8,%9}, {%0,%1,%2,%3};"
      : "+f"(c[0]), "+f"(c[1]), "+f"(c[2]), "+f"(c[3])
      : "r"(a[0]), "r"(a[1]), "r"(a[2]), "r"(a[3]), "r"(b0), "r"(b1));
}

// ---------------- pre-pass: fp32 K,V -> bf16 hi/lo planes ----------------
__global__ void __launch_bounds__(256)
conv_kernel(const float* __restrict__ k, const float* __restrict__ v) {
  size_t i = (size_t)blockIdx.x * 256 + threadIdx.x;  // float4 index
  float4 a = ((const float4*)k)[i];
  float4 b = ((const float4*)v)[i];
  __nv_bfloat16 h0, h1, h2, h3, l0, l1, l2, l3;
  split2(a.x, h0, l0); split2(a.y, h1, l1); split2(a.z, h2, l2); split2(a.w, h3, l3);
  ((uint2*)g_KH)[i] = make_uint2(pack2(h0, h1), pack2(h2, h3));
  ((uint2*)g_KL)[i] = make_uint2(pack2(l0, l1), pack2(l2, l3));
  split2(b.x, h0, l0); split2(b.y, h1, l1); split2(b.z, h2, l2); split2(b.w, h3, l3);
  ((uint2*)g_VH)[i] = make_uint2(pack2(h0, h1), pack2(h2, h3));
  ((uint2*)g_VL)[i] = make_uint2(pack2(l0, l1), pack2(l2, l3));
}

__global__ void __launch_bounds__(NTHREADS, 1)
attn_mask_kernel(const float* __restrict__ q, const float* __restrict__ mask,
                 float* __restrict__ out) {
  extern __shared__ char smem[];
  const uint32_t sb = smem_u32(smem);
  const int tid = threadIdx.x, wid = tid >> 5, lane = tid & 31;
  const int bh = (int)blockIdx.z * Hh + (int)blockIdx.y;
  const int s0 = (int)blockIdx.x * TM;

  char* QH = smem;
  char* QL = smem + TILE_B;
  const uint32_t sKH = sb + 2 * TILE_B;
  const uint32_t sKL = sb + 3 * TILE_B;
  const uint32_t sVH = sb + 4 * TILE_B;
  const uint32_t sVL = sb + 5 * TILE_B;

  const __nv_bfloat16* kh = g_KH + (size_t)bh * Ss * Dd;
  const __nv_bfloat16* kl = g_KL + (size_t)bh * Ss * Dd;
  const __nv_bfloat16* vh = g_VH + (size_t)bh * Ss * Dd;
  const __nv_bfloat16* vl = g_VL + (size_t)bh * Ss * Dd;

  // ---- load + split Q tile (once) ----
  {
    const float4* qsrc = (const float4*)(q + ((size_t)bh * Ss + s0) * Dd);
#pragma unroll
    for (int i = 0; i < 8; ++i) {
      int f = tid + i * NTHREADS;
      float4 val = qsrc[f];
      int e = f * 4;
      store_hl4(QH, QL, e >> 7, e & 127, val);
    }
  }

  // ---- prologue: async-load tile 0 K and V ----
  load_tile_pair(sKH, sKL, kh, kl, tid);
  CP_COMMIT();
  load_tile_pair(sVH, sVL, vh, vl, tid);
  CP_COMMIT();
  CP_WAIT1();          // K(0) done (V(0) may be in flight)
  __syncthreads();

  // warp tiling: wi = 16-row strip, wj = t-half (64 cols of the 128-wide k tile)
  const int wi = wid >> 1;
  const int wj = wid & 1;
  const int wrow0 = wi * 16;
  const int tcol0 = wj * 64;

  // accumulators: S [8 n-frags][4] (warp's t-half), O [16 n-frags][4] partial over t-half
  float S[8][4];
  float O[16][4];
#pragma unroll
  for (int i = 0; i < 16; ++i) { O[i][0] = O[i][1] = O[i][2] = O[i][3] = 0.f; }

  const int lrow = lane & 7;
  const int lq = (lane >> 3) & 1;
  const int lh = lane >> 4;

  // ldmatrix lane base addresses
  const uint32_t qA_h = sb + 0 * TILE_B + toff(wrow0 + lrow + lq * 8, lh * 8);
  const uint32_t qA_l = qA_h + TILE_B;
  // K B-frags: t-rows from this warp's t-half
  const uint32_t kB_h = sKH + toff(tcol0 + lrow + lh * 8, lq * 8);
  const uint32_t kB_l = kB_h + TILE_B;
  // V B-frags (trans): t-rows from this warp's t-half, all 128 d-cols
  const uint32_t vB_h = sVH + toff(tcol0 + lrow + lq * 8, lh * 8);
  const uint32_t vB_l = vB_h + TILE_B;

  const int mr = wrow0 + (lane >> 2);      // this thread's row (and +8)
  const int mc = (lane & 3) * 2;           // col offset within an 8-wide n-frag
  const float* mbase = mask + ((size_t)bh * Ss + (s0 + mr)) * Ss + tcol0;

#pragma unroll 1
  for (int kt = 0; kt < NKT; ++kt) {
    const int t0 = kt * TN;
    const int tn = (kt + 1 < NKT) ? (kt + 1) * TN : 0;  // clamp (harmless reload)

    // ---- GEMM1: S[16 x 64] = Q @ K[t-half]^T (3-term bf16 split) ----
#pragma unroll
    for (int i = 0; i < 8; ++i) { S[i][0] = S[i][1] = S[i][2] = S[i][3] = 0.f; }
#pragma unroll
    for (int kk = 0; kk < 8; ++kk) {
      uint32_t ah[4], al[4];
      ldsm4(ah, qA_h + kk * 32);
      ldsm4(al, qA_l + kk * 32);
#pragma unroll
      for (int ntp = 0; ntp < 4; ++ntp) {
        uint32_t bh_[4], bl_[4];
        ldsm4(bh_, kB_h + (uint32_t)(ntp * 16 * ROWB) + kk * 32);
        ldsm4(bl_, kB_l + (uint32_t)(ntp * 16 * ROWB) + kk * 32);
        mma16816(S[2 * ntp],     ah, bh_[0], bh_[1]);
        mma16816(S[2 * ntp + 1], ah, bh_[2], bh_[3]);
        mma16816(S[2 * ntp],     ah, bl_[0], bl_[1]);
        mma16816(S[2 * ntp + 1], ah, bl_[2], bl_[3]);
        mma16816(S[2 * ntp],     al, bh_[0], bh_[1]);
        mma16816(S[2 * ntp + 1], al, bh_[2], bh_[3]);
      }
    }

    __syncthreads();  // all warps done reading K tile

    // ---- issue next K tile (overlaps GEMM2) ----
    load_tile_pair(sKH, sKL, kh + (size_t)tn * Dd, kl + (size_t)tn * Dd, tid);
    CP_COMMIT();
    CP_WAIT1();       // V(kt) done (next-K outstanding)
    __syncthreads();

    // ---- GEMM2: O(partial) += (S*mask) @ V[t-half, :] ----
#pragma unroll
    for (int kk = 0; kk < 4; ++kk) {
      // mask for n-frags 2kk, 2kk+1 (inline; 4-warp/SMSP overlap hides latency)
      {
        const float* mp0 = mbase + t0 + (2 * kk) * 8 + mc;
        const float* mp1 = mbase + t0 + (2 * kk + 1) * 8 + mc;
        float2 m0 = __ldcs((const float2*)mp0);
        float2 m1 = __ldcs((const float2*)(mp0 + 8 * Ss));
        float2 m2 = __ldcs((const float2*)mp1);
        float2 m3 = __ldcs((const float2*)(mp1 + 8 * Ss));
        S[2 * kk][0] *= m0.x;     S[2 * kk][1] *= m0.y;
        S[2 * kk][2] *= m1.x;     S[2 * kk][3] *= m1.y;
        S[2 * kk + 1][0] *= m2.x; S[2 * kk + 1][1] *= m2.y;
        S[2 * kk + 1][2] *= m3.x; S[2 * kk + 1][3] *= m3.y;
      }
      // build P A-fragments (k = tcol0 + kk*16 — matches this warp's S cols)
      uint32_t ph[4], pl[4];
      {
        __nv_bfloat16 h0, h1, h2, h3, l0, l1, l2, l3;
        split2(S[2 * kk][0], h0, l0); split2(S[2 * kk][1], h1, l1);
        split2(S[2 * kk][2], h2, l2); split2(S[2 * kk][3], h3, l3);
        ph[0] = pack2(h0, h1); ph[1] = pack2(h2, h3);
        pl[0] = pack2(l0, l1); pl[1] = pack2(l2, l3);
        split2(S[2 * kk + 1][0], h0, l0); split2(S[2 * kk + 1][1], h1, l1);
        split2(S[2 * kk + 1][2], h2, l2); split2(S[2 * kk + 1][3], h3, l3);
        ph[2] = pack2(h0, h1); ph[3] = pack2(h2, h3);
        pl[2] = pack2(l0, l1); pl[3] = pack2(l2, l3);
      }
#pragma unroll
      for (int np = 0; np < 8; ++np) {
        uint32_t bh_[4], bl_[4];
        ldsm4t(bh_, vB_h + (uint32_t)(kk * 16 * ROWB) + np * 32);
        ldsm4t(bl_, vB_l + (uint32_t)(kk * 16 * ROWB) + np * 32);
        mma16816(O[2 * np],     ph, bh_[0], bh_[1]);
        mma16816(O[2 * np + 1], ph, bh_[2], bh_[3]);
        mma16816(O[2 * np],     ph, bl_[0], bl_[1]);
        mma16816(O[2 * np + 1], ph, bl_[2], bl_[3]);
        mma16816(O[2 * np],     pl, bh_[0], bh_[1]);
        mma16816(O[2 * np + 1], pl, bh_[2], bh_[3]);
      }
    }

    __syncthreads();  // all warps done reading V tile

    // ---- issue next V tile (overlaps next GEMM1) ----
    load_tile_pair(sVH, sVL, vh + (size_t)tn * Dd, vl + (size_t)tn * Dd, tid);
    CP_COMMIT();
    CP_WAIT1();       // next-K done (next-V outstanding)
    __syncthreads();
  }

  // ---- quiesce all outstanding cp.async before repurposing smem ----
  CP_WAIT0();
  __syncthreads();

  // ---- epilogue: combine warp-pair partial O via smem, then -> gmem ----
  {
    float* SP = (float*)(smem + 2 * TILE_B);   // K/V buffers dead; 128 x 132 floats
    if (wj == 1) {
#pragma unroll
      for (int nf = 0; nf < 16; ++nf) {
        SP[mr * 132 + nf * 8 + mc] = O[nf][0];
        SP[mr * 132 + nf * 8 + mc + 1] = O[nf][1];
        SP[(mr + 8) * 132 + nf * 8 + mc] = O[nf][2];
        SP[(mr + 8) * 132 + nf * 8 + mc + 1] = O[nf][3];
      }
    }
    __syncthreads();
    if (wj == 0) {
      float* ob = out + ((size_t)bh * Ss + (s0 + mr)) * Dd + mc;
#pragma unroll
      for (int nf = 0; nf < 16; ++nf) {
        float2 r0 = make_float2(O[nf][0] + SP[mr * 132 + nf * 8 + mc],
                                O[nf][1] + SP[mr * 132 + nf * 8 + mc + 1]);
        float2 r1 = make_float2(O[nf][2] + SP[(mr + 8) * 132 + nf * 8 + mc],
                                O[nf][3] + SP[(mr + 8) * 132 + nf * 8 + mc + 1]);
        *(float2*)(ob + nf * 8) = r0;
        *(float2*)(ob + 8 * Dd + nf * 8) = r1;
      }
    }
  }
}

}  // namespace

extern "C" void kernel_launch(void* const* d_in, const int* in_sizes, int n_in,
                              void* d_out, int out_size) {
  (void)in_sizes; (void)n_in; (void)out_size;
  const float* q = (const float*)d_in[0];
  const float* k = (const float*)d_in[1];
  const float* v = (const float*)d_in[2];
  const float* m = (const float*)d_in[3];
  float* out = (float*)d_out;

  // pre-pass: convert K, V to bf16 hi/lo planes (NELEM/4 float4s, 256 thr/blk)
  conv_kernel<<<(int)(NELEM / 4 / 256), 256>>>(k, v);

  cudaFuncSetAttribute(attn_mask_kernel, cudaFuncAttributeMaxDynamicSharedMemorySize,
                       SMEM_BYTES);
  dim3 grid(Ss / TM, Hh, Bb);
  attn_mask_kernel<<<grid, NTHREADS, SMEM_BYTES>>>(q, m, out);
}